// round 1
// baseline (speedup 1.0000x reference)
#include <cuda_runtime.h>
#include <stdint.h>

#define NN 65536
#define DD 256
#define KK 4096

#define BM 128
#define BN 128
#define BK 32
#define AP 132   // padded pitch for transposed A tile (rows dim)
#define BP 132   // padded pitch for transposed B tile (cols dim)

// scratch (static __device__ — no allocation)
__device__ float g_acc[KK * DD];   // running numerator: c0*centers + seg_sum
__device__ float g_cntf[KK];       // running denominator: c0 + seg_cnt
__device__ float g_c2[KK];         // ||center||^2
__device__ float g_loss;

// ---------------------------------------------------------------------------
// init: g_acc = counts*centers, g_cntf = counts, g_c2 = sum(c^2), loss = 0
// ---------------------------------------------------------------------------
__global__ void init_kernel(const float* __restrict__ centers,
                            const int* __restrict__ counts) {
    int k = blockIdx.x;
    int d = threadIdx.x;             // 256 threads
    float c = centers[(size_t)k * DD + d];
    float cnt = (float)counts[k];
    g_acc[(size_t)k * DD + d] = cnt * c;

    __shared__ float red[8];
    float v = c * c;
    #pragma unroll
    for (int off = 16; off > 0; off >>= 1)
        v += __shfl_down_sync(0xffffffffu, v, off);
    if ((d & 31) == 0) red[d >> 5] = v;
    __syncthreads();
    if (d == 0) {
        float s = 0.f;
        #pragma unroll
        for (int w = 0; w < 8; ++w) s += red[w];
        g_c2[k] = s;
        g_cntf[k] = cnt;
        if (k == 0) g_loss = 0.f;
    }
}

// ---------------------------------------------------------------------------
// fused GEMM + argmin + loss + segment-sum scatter
// block = 128 rows; loops over all 4096 centers in 128-col tiles.
// ---------------------------------------------------------------------------
__global__ void __launch_bounds__(256, 1)
assign_kernel(const float* __restrict__ emb,
              const float* __restrict__ centers,
              float* __restrict__ labels_out) {
    extern __shared__ float sm[];
    float* At    = sm;                       // [256][AP] transposed A (k-major)
    float* Bst   = At + 256 * AP;            // [2][BK][BP] transposed B, dbl buf
    float* x2s   = Bst + 2 * BK * BP;        // [128]
    float* loss_s = x2s + BM;                // [128]
    int*   lab_s  = (int*)(loss_s + BM);     // [128]

    const int tid = threadIdx.x;
    const int tx = tid & 15;
    const int ty = tid >> 4;
    const int row0 = blockIdx.x * BM;

    if (tid < BM) x2s[tid] = 0.f;

    // load A transposed: At[k][r] = emb[row0+r][k]  (coalesced global float4)
    #pragma unroll
    for (int it = 0; it < 32; ++it) {
        int f = it * 256 + tid;
        int r = f >> 6;            // 0..127
        int k4 = f & 63;           // 0..63
        float4 v = *reinterpret_cast<const float4*>(
            &emb[(size_t)(row0 + r) * DD + k4 * 4]);
        At[(k4 * 4 + 0) * AP + r] = v.x;
        At[(k4 * 4 + 1) * AP + r] = v.y;
        At[(k4 * 4 + 2) * AP + r] = v.z;
        At[(k4 * 4 + 3) * AP + r] = v.w;
    }
    __syncthreads();

    // x2 per row (2 threads/row, conflict-free lanes over r)
    {
        int r = tid & 127;
        int kbase = (tid >> 7) * 128;
        float s = 0.f;
        #pragma unroll 8
        for (int k = 0; k < 128; ++k) {
            float a = At[(kbase + k) * AP + r];
            s = fmaf(a, a, s);
        }
        atomicAdd(&x2s[r], s);
    }

    float bestv[8];
    int   bestj[8];
    #pragma unroll
    for (int i = 0; i < 8; ++i) { bestv[i] = 3.4e38f; bestj[i] = 0; }

    for (int j0 = 0; j0 < KK; j0 += BN) {
        float acc[8][8];
        #pragma unroll
        for (int i = 0; i < 8; ++i)
            #pragma unroll
            for (int j = 0; j < 8; ++j) acc[i][j] = 0.f;

        float4 ldreg[4];
        // prologue: load k-tile 0 of this column tile into buf 0
        #pragma unroll
        for (int q = 0; q < 4; ++q) {
            int f = q * 256 + tid;
            int jj = f >> 3, kk4 = f & 7;
            ldreg[q] = *reinterpret_cast<const float4*>(
                &centers[(size_t)(j0 + jj) * DD + kk4 * 4]);
        }
        #pragma unroll
        for (int q = 0; q < 4; ++q) {
            int f = q * 256 + tid;
            int jj = f >> 3, kk4 = f & 7;
            Bst[(kk4 * 4 + 0) * BP + jj] = ldreg[q].x;
            Bst[(kk4 * 4 + 1) * BP + jj] = ldreg[q].y;
            Bst[(kk4 * 4 + 2) * BP + jj] = ldreg[q].z;
            Bst[(kk4 * 4 + 3) * BP + jj] = ldreg[q].w;
        }
        __syncthreads();

        #pragma unroll 1
        for (int t = 0; t < DD / BK; ++t) {
            const int buf = t & 1;
            if (t < DD / BK - 1) {
                int k0n = (t + 1) * BK;
                #pragma unroll
                for (int q = 0; q < 4; ++q) {
                    int f = q * 256 + tid;
                    int jj = f >> 3, kk4 = f & 7;
                    ldreg[q] = *reinterpret_cast<const float4*>(
                        &centers[(size_t)(j0 + jj) * DD + k0n + kk4 * 4]);
                }
            }
            const float* Bp = Bst + buf * BK * BP;
            #pragma unroll
            for (int kk = 0; kk < BK; ++kk) {
                const int kabs = t * BK + kk;
                const float4 a0 = *reinterpret_cast<const float4*>(&At[kabs * AP + ty * 4]);
                const float4 a1 = *reinterpret_cast<const float4*>(&At[kabs * AP + 64 + ty * 4]);
                const float4 b0 = *reinterpret_cast<const float4*>(&Bp[kk * BP + tx * 4]);
                const float4 b1 = *reinterpret_cast<const float4*>(&Bp[kk * BP + 64 + tx * 4]);
                const float a[8] = {a0.x, a0.y, a0.z, a0.w, a1.x, a1.y, a1.z, a1.w};
                const float b[8] = {b0.x, b0.y, b0.z, b0.w, b1.x, b1.y, b1.z, b1.w};
                #pragma unroll
                for (int i = 0; i < 8; ++i)
                    #pragma unroll
                    for (int j = 0; j < 8; ++j)
                        acc[i][j] = fmaf(a[i], b[j], acc[i][j]);
            }
            if (t < DD / BK - 1) {
                float* Bw = Bst + (buf ^ 1) * BK * BP;
                #pragma unroll
                for (int q = 0; q < 4; ++q) {
                    int f = q * 256 + tid;
                    int jj = f >> 3, kk4 = f & 7;
                    Bw[(kk4 * 4 + 0) * BP + jj] = ldreg[q].x;
                    Bw[(kk4 * 4 + 1) * BP + jj] = ldreg[q].y;
                    Bw[(kk4 * 4 + 2) * BP + jj] = ldreg[q].z;
                    Bw[(kk4 * 4 + 3) * BP + jj] = ldreg[q].w;
                }
            }
            __syncthreads();
        }

        // epilogue: t = c2 - 2*dot ; running argmin
        #pragma unroll
        for (int j = 0; j < 8; ++j) {
            const int col = j0 + ((j < 4) ? (tx * 4 + j) : (64 + tx * 4 + j - 4));
            const float c2v = __ldg(&g_c2[col]);
            #pragma unroll
            for (int i = 0; i < 8; ++i) {
                float v = fmaf(-2.f, acc[i][j], c2v);
                if (v < bestv[i]) { bestv[i] = v; bestj[i] = col; }
            }
        }
    }

    // cross-thread argmin reduce over the 16 tx lanes (width-16 groups)
    #pragma unroll
    for (int i = 0; i < 8; ++i) {
        float v = bestv[i];
        int j = bestj[i];
        #pragma unroll
        for (int off = 8; off > 0; off >>= 1) {
            float ov = __shfl_down_sync(0xffffffffu, v, off, 16);
            int   oj = __shfl_down_sync(0xffffffffu, j, off, 16);
            if (ov < v || (ov == v && oj < j)) { v = ov; j = oj; }
        }
        if (tx == 0) {
            const int r = (i < 4) ? (ty * 4 + i) : (64 + ty * 4 + i - 4);
            lab_s[r] = j;
            loss_s[r] = x2s[r] + v;         // = ||x - c_j||^2
            labels_out[row0 + r] = (float)j;
        }
    }
    __syncthreads();

    // block loss -> one atomic
    if (tid == 0) {
        float s = 0.f;
        #pragma unroll 4
        for (int r = 0; r < BM; ++r) s += loss_s[r];
        atomicAdd(&g_loss, s);
    }
    // counts
    if (tid < BM) atomicAdd(&g_cntf[lab_s[tid]], 1.0f);
    // segment-sum scatter: rows are in smem (At), coalesced REDG per row
    for (int r = 0; r < BM; ++r) {
        const int lab = lab_s[r];
        atomicAdd(&g_acc[(size_t)lab * DD + tid], At[tid * AP + r]);
    }
}

// ---------------------------------------------------------------------------
// finalize: centers / counts / loss into output buffer
// layout: [labels N][centers K*D][counts K][loss 1], all fp32
// ---------------------------------------------------------------------------
__global__ void finalize_kernel(float* __restrict__ out) {
    int k = blockIdx.x;
    int d = threadIdx.x;
    float cnt = g_cntf[k];
    out[(size_t)NN + (size_t)k * DD + d] = g_acc[(size_t)k * DD + d] / cnt;
    if (d == 0) out[(size_t)NN + (size_t)KK * DD + k] = cnt;  // exact int in fp32
    if (k == 0 && d == 0)
        out[(size_t)NN + (size_t)KK * DD + KK] = g_loss / (float)NN;
}

// ---------------------------------------------------------------------------
extern "C" void kernel_launch(void* const* d_in, const int* in_sizes, int n_in,
                              void* d_out, int out_size) {
    const float* emb     = (const float*)d_in[0];
    const float* centers = (const float*)d_in[1];
    const int*   counts  = (const int*)d_in[2];
    float* out = (float*)d_out;

    const int smem_bytes = (256 * AP + 2 * BK * BP + BM + BM + BM) * 4;
    cudaFuncSetAttribute(assign_kernel,
                         cudaFuncAttributeMaxDynamicSharedMemorySize, smem_bytes);

    init_kernel<<<KK, 256>>>(centers, counts);
    assign_kernel<<<NN / BM, 256, smem_bytes>>>(emb, centers, out);
    finalize_kernel<<<KK, DD>>>(out);
}

// round 2
// speedup vs baseline: 1.6378x; 1.6378x over previous
#include <cuda_runtime.h>
#include <stdint.h>

#define NN 65536
#define DD 256
#define KK 4096

#define BM 128
#define BN 128
#define BK 32
#define AP 132   // padded pitch for transposed A tile (rows dim)
#define BP 132   // padded pitch for transposed B tile (cols dim)

// scratch (static __device__ — no allocation)
__device__ float g_acc[KK * DD];   // running numerator: c0*centers + seg_sum
__device__ float g_cntf[KK];       // running denominator: c0 + seg_cnt
__device__ float g_c2[KK];         // ||center||^2
__device__ float g_loss;

// ---------------------------------------------------------------------------
// init: g_acc = counts*centers, g_cntf = counts, g_c2 = sum(c^2), loss = 0
// ---------------------------------------------------------------------------
__global__ void init_kernel(const float* __restrict__ centers,
                            const int* __restrict__ counts) {
    int k = blockIdx.x;
    int d = threadIdx.x;             // 256 threads
    float c = centers[(size_t)k * DD + d];
    float cnt = (float)counts[k];
    g_acc[(size_t)k * DD + d] = cnt * c;

    __shared__ float red[8];
    float v = c * c;
    #pragma unroll
    for (int off = 16; off > 0; off >>= 1)
        v += __shfl_down_sync(0xffffffffu, v, off);
    if ((d & 31) == 0) red[d >> 5] = v;
    __syncthreads();
    if (d == 0) {
        float s = 0.f;
        #pragma unroll
        for (int w = 0; w < 8; ++w) s += red[w];
        g_c2[k] = s;
        g_cntf[k] = cnt;
        if (k == 0) g_loss = 0.f;
    }
}

// ---------------------------------------------------------------------------
// fused GEMM + argmin + loss + segment-sum scatter
// block = 128 rows; loops over all 4096 centers in 128-col tiles.
// ---------------------------------------------------------------------------
__global__ void __launch_bounds__(256, 1)
assign_kernel(const float* __restrict__ emb,
              const float* __restrict__ centers,
              float* __restrict__ labels_out) {
    extern __shared__ float sm[];
    float* At    = sm;                       // [256][AP] transposed A (k-major)
    float* Bst   = At + 256 * AP;            // [2][BK][BP] transposed B, dbl buf
    float* x2s   = Bst + 2 * BK * BP;        // [128]
    float* loss_s = x2s + BM;                // [128]
    int*   lab_s  = (int*)(loss_s + BM);     // [128]

    const int tid = threadIdx.x;
    const int tx = tid & 15;
    const int ty = tid >> 4;
    const int row0 = blockIdx.x * BM;

    if (tid < BM) x2s[tid] = 0.f;

    // load A transposed: At[k][r] = emb[row0+r][k]  (coalesced global float4)
    #pragma unroll
    for (int it = 0; it < 32; ++it) {
        int f = it * 256 + tid;
        int r = f >> 6;            // 0..127
        int k4 = f & 63;           // 0..63
        float4 v = *reinterpret_cast<const float4*>(
            &emb[(size_t)(row0 + r) * DD + k4 * 4]);
        At[(k4 * 4 + 0) * AP + r] = v.x;
        At[(k4 * 4 + 1) * AP + r] = v.y;
        At[(k4 * 4 + 2) * AP + r] = v.z;
        At[(k4 * 4 + 3) * AP + r] = v.w;
    }
    __syncthreads();

    // x2 per row (2 threads/row, conflict-free lanes over r)
    {
        int r = tid & 127;
        int kbase = (tid >> 7) * 128;
        float s = 0.f;
        #pragma unroll 8
        for (int k = 0; k < 128; ++k) {
            float a = At[(kbase + k) * AP + r];
            s = fmaf(a, a, s);
        }
        atomicAdd(&x2s[r], s);
    }

    float bestv[8];
    int   bestj[8];
    #pragma unroll
    for (int i = 0; i < 8; ++i) { bestv[i] = 3.4e38f; bestj[i] = 0; }

    for (int j0 = 0; j0 < KK; j0 += BN) {
        float acc[8][8];
        #pragma unroll
        for (int i = 0; i < 8; ++i)
            #pragma unroll
            for (int j = 0; j < 8; ++j) acc[i][j] = 0.f;

        float4 ldreg[4];
        // prologue: load k-tile 0 of this column tile into buf 0
        #pragma unroll
        for (int q = 0; q < 4; ++q) {
            int f = q * 256 + tid;
            int jj = f >> 3, kk4 = f & 7;
            ldreg[q] = *reinterpret_cast<const float4*>(
                &centers[(size_t)(j0 + jj) * DD + kk4 * 4]);
        }
        #pragma unroll
        for (int q = 0; q < 4; ++q) {
            int f = q * 256 + tid;
            int jj = f >> 3, kk4 = f & 7;
            Bst[(kk4 * 4 + 0) * BP + jj] = ldreg[q].x;
            Bst[(kk4 * 4 + 1) * BP + jj] = ldreg[q].y;
            Bst[(kk4 * 4 + 2) * BP + jj] = ldreg[q].z;
            Bst[(kk4 * 4 + 3) * BP + jj] = ldreg[q].w;
        }
        __syncthreads();

        #pragma unroll 1
        for (int t = 0; t < DD / BK; ++t) {
            const int buf = t & 1;
            if (t < DD / BK - 1) {
                int k0n = (t + 1) * BK;
                #pragma unroll
                for (int q = 0; q < 4; ++q) {
                    int f = q * 256 + tid;
                    int jj = f >> 3, kk4 = f & 7;
                    ldreg[q] = *reinterpret_cast<const float4*>(
                        &centers[(size_t)(j0 + jj) * DD + k0n + kk4 * 4]);
                }
            }
            const float* Bp = Bst + buf * BK * BP;
            #pragma unroll
            for (int kk = 0; kk < BK; ++kk) {
                const int kabs = t * BK + kk;
                const float4 a0 = *reinterpret_cast<const float4*>(&At[kabs * AP + ty * 4]);
                const float4 a1 = *reinterpret_cast<const float4*>(&At[kabs * AP + 64 + ty * 4]);
                const float4 b0 = *reinterpret_cast<const float4*>(&Bp[kk * BP + tx * 4]);
                const float4 b1 = *reinterpret_cast<const float4*>(&Bp[kk * BP + 64 + tx * 4]);
                const float a[8] = {a0.x, a0.y, a0.z, a0.w, a1.x, a1.y, a1.z, a1.w};
                const float b[8] = {b0.x, b0.y, b0.z, b0.w, b1.x, b1.y, b1.z, b1.w};
                #pragma unroll
                for (int i = 0; i < 8; ++i)
                    #pragma unroll
                    for (int j = 0; j < 8; ++j)
                        acc[i][j] = fmaf(a[i], b[j], acc[i][j]);
            }
            if (t < DD / BK - 1) {
                float* Bw = Bst + (buf ^ 1) * BK * BP;
                #pragma unroll
                for (int q = 0; q < 4; ++q) {
                    int f = q * 256 + tid;
                    int jj = f >> 3, kk4 = f & 7;
                    Bw[(kk4 * 4 + 0) * BP + jj] = ldreg[q].x;
                    Bw[(kk4 * 4 + 1) * BP + jj] = ldreg[q].y;
                    Bw[(kk4 * 4 + 2) * BP + jj] = ldreg[q].z;
                    Bw[(kk4 * 4 + 3) * BP + jj] = ldreg[q].w;
                }
            }
            __syncthreads();
        }

        // epilogue: t = c2 - 2*dot ; running argmin
        #pragma unroll
        for (int j = 0; j < 8; ++j) {
            const int col = j0 + ((j < 4) ? (tx * 4 + j) : (64 + tx * 4 + j - 4));
            const float c2v = __ldg(&g_c2[col]);
            #pragma unroll
            for (int i = 0; i < 8; ++i) {
                float v = fmaf(-2.f, acc[i][j], c2v);
                if (v < bestv[i]) { bestv[i] = v; bestj[i] = col; }
            }
        }
    }

    // cross-thread argmin reduce over the 16 tx lanes (width-16 groups)
    #pragma unroll
    for (int i = 0; i < 8; ++i) {
        float v = bestv[i];
        int j = bestj[i];
        #pragma unroll
        for (int off = 8; off > 0; off >>= 1) {
            float ov = __shfl_down_sync(0xffffffffu, v, off, 16);
            int   oj = __shfl_down_sync(0xffffffffu, j, off, 16);
            if (ov < v || (ov == v && oj < j)) { v = ov; j = oj; }
        }
        if (tx == 0) {
            const int r = (i < 4) ? (ty * 4 + i) : (64 + ty * 4 + i - 4);
            lab_s[r] = j;
            loss_s[r] = x2s[r] + v;         // = ||x - c_j||^2
            labels_out[row0 + r] = (float)j;
        }
    }
    __syncthreads();

    // block loss -> one atomic
    if (tid == 0) {
        float s = 0.f;
        #pragma unroll 4
        for (int r = 0; r < BM; ++r) s += loss_s[r];
        atomicAdd(&g_loss, s);
    }
    // counts
    if (tid < BM) atomicAdd(&g_cntf[lab_s[tid]], 1.0f);
    // segment-sum scatter: rows are in smem (At), coalesced REDG per row
    for (int r = 0; r < BM; ++r) {
        const int lab = lab_s[r];
        atomicAdd(&g_acc[(size_t)lab * DD + tid], At[tid * AP + r]);
    }
}

// ---------------------------------------------------------------------------
// finalize: centers / counts / loss into output buffer
// layout: [labels N][centers K*D][counts K][loss 1], all fp32
// ---------------------------------------------------------------------------
__global__ void finalize_kernel(float* __restrict__ out) {
    int k = blockIdx.x;
    int d = threadIdx.x;
    float cnt = g_cntf[k];
    out[(size_t)NN + (size_t)k * DD + d] = g_acc[(size_t)k * DD + d] / cnt;
    if (d == 0) out[(size_t)NN + (size_t)KK * DD + k] = cnt;  // exact int in fp32
    if (k == 0 && d == 0)
        out[(size_t)NN + (size_t)KK * DD + KK] = g_loss / (float)NN;
}

// ---------------------------------------------------------------------------
extern "C" void kernel_launch(void* const* d_in, const int* in_sizes, int n_in,
                              void* d_out, int out_size) {
    const float* emb     = (const float*)d_in[0];
    const float* centers = (const float*)d_in[1];
    const int*   counts  = (const int*)d_in[2];
    float* out = (float*)d_out;

    const int smem_bytes = (256 * AP + 2 * BK * BP + BM + BM + BM) * 4;
    cudaFuncSetAttribute(assign_kernel,
                         cudaFuncAttributeMaxDynamicSharedMemorySize, smem_bytes);

    init_kernel<<<KK, 256>>>(centers, counts);
    assign_kernel<<<NN / BM, 256, smem_bytes>>>(emb, centers, out);
    finalize_kernel<<<KK, DD>>>(out);
}